// round 15
// baseline (speedup 1.0000x reference)
#include <cuda_runtime.h>
#include <cuda_fp16.h>
#include <cstdint>

// CapsuleLayer: B=32, I=32, C=2048, U=64, O=32, 3 routing iterations.
// R15 = R14 + ONE delta: gemm 3-stage cp.async ring WITH tail drain fixed
// (empty commit_group each tail iteration keeps wait_group 1 draining tiles
// 62/63 — the missing piece that corrupted R12/R13).
//  k_gemm_mma : fp16 mma.sync m16n8k16; 3-stage W ring (fixed); s1 fused.
//  k_squash   : reduce s partials -> squash -> v (+ optional fp16 copy).
//  k_fused    : 2-CTA cluster, 2-stage staging, o-quad map [proven, 78.5us].

__device__ __half g_uhat[134217728];  // 256 MB (c,b,u,o): c*65536 + b*2048 + uo
__device__ float g_sparts[16777216];  // 256 slots x 65536 (b*2048 + uo)
__device__ __half g_vh[65536];        // v fp16 (b,u,o)
__device__ float g_b[131072];         // routing logits (C,U)

__global__ void k_nop() {}

// ---------------- gemm ----------------
// smem: W stages 3x32KB | x_h 8x2KB => 112KB/CTA, 2 CTAs/SM (224KB/SM)
#define GM_XH 98304
#define GM_TOT 114688

__device__ __forceinline__ void mma16816(float d[4], uint32_t a0, uint32_t a1,
                                         uint32_t a2, uint32_t a3,
                                         uint32_t b0, uint32_t b1) {
    asm volatile(
        "mma.sync.aligned.m16n8k16.row.col.f32.f16.f16.f32 "
        "{%0,%1,%2,%3}, {%4,%5,%6,%7}, {%8,%9}, {%0,%1,%2,%3};"
        : "+f"(d[0]), "+f"(d[1]), "+f"(d[2]), "+f"(d[3])
        : "r"(a0), "r"(a1), "r"(a2), "r"(a3), "r"(b0), "r"(b1));
}

__global__ __launch_bounds__(256, 2) void k_gemm_mma(const float* __restrict__ x,
                                                     const float* __restrict__ w) {
    extern __shared__ char smem[];
    float* wsm = reinterpret_cast<float*>(smem);
    __half* x_h = reinterpret_cast<__half*>(smem + GM_XH);
    const int tid = threadIdx.x;
    const int warp = tid >> 5, lane = tid & 31;
    const int r = lane >> 2, q = lane & 3;
    const int c0 = blockIdx.x * 8;

    // tile n: channel c0+(n&7), p-rows (n>>3)*256..+255, buffer n%3
    auto issue = [&](int n) {
        const float* src = w + ((long)(c0 + (n & 7)) * 2048 + (long)(n >> 3) * 256) * 32;
        char* dst = smem + (n % 3) * 32768;
#pragma unroll
        for (int it = 0; it < 8; it++) {
            int lin = it * 256 + tid;
            int row = lin >> 3, cq = lin & 7;
            int col = cq ^ ((row & 1) << 2);   // parity swizzle -> conflict-free LDS.128
            asm volatile("cp.async.cg.shared.global [%0], [%1], 16;"
                :: "r"((uint32_t)__cvta_generic_to_shared(dst + row * 128 + col * 16)),
                   "l"(src + row * 32 + cq * 4) : "memory");
        }
        asm volatile("cp.async.commit_group;" ::: "memory");
    };
    issue(0);
    issue(1);

    // Stage x -> fp16 smem: x_h[cc][b][i]
    for (int idx = tid; idx < 8192; idx += 256) {
        int cc = idx & 7, bi = idx >> 3;
        x_h[cc * 1024 + bi] = __float2half_rn(x[bi * 2048 + c0 + cc]);
    }

    float sacc[4][2][4];

    for (int n = 0; n < 64; n++) {
        const int cc = n & 7, chunk = n >> 3;
        const int c = c0 + cc;

        asm volatile("cp.async.wait_group 1;" ::: "memory");  // tile n landed
        __syncthreads();                 // visible to all warps (+ x_h at n=0)
        if (n + 2 < 64) issue(n + 2);
        else asm volatile("cp.async.commit_group;" ::: "memory");  // TAIL DRAIN FIX

        if (cc == 0) {
#pragma unroll
            for (int nt = 0; nt < 4; nt++)
#pragma unroll
                for (int bt = 0; bt < 2; bt++)
#pragma unroll
                    for (int jj = 0; jj < 4; jj++) sacc[nt][bt][jj] = 0.f;
        }

        // A fragments (logical-k permutation; matches B below)
        uint32_t A[2][2][4];
#pragma unroll
        for (int bt = 0; bt < 2; bt++)
#pragma unroll
            for (int ks = 0; ks < 2; ks++) {
                uint2 v1 = *reinterpret_cast<const uint2*>(
                    &x_h[cc * 1024 + (bt * 16 + r) * 32 + ks * 16 + q * 4]);
                uint2 v2 = *reinterpret_cast<const uint2*>(
                    &x_h[cc * 1024 + (bt * 16 + r + 8) * 32 + ks * 16 + q * 4]);
                A[bt][ks][0] = v1.x;
                A[bt][ks][1] = v2.x;
                A[bt][ks][2] = v1.y;
                A[bt][ks][3] = v2.y;
            }

        float d[4][2][4];
#pragma unroll
        for (int nt = 0; nt < 4; nt++)
#pragma unroll
            for (int bt = 0; bt < 2; bt++)
#pragma unroll
                for (int jj = 0; jj < 4; jj++) d[nt][bt][jj] = 0.f;

        const float* wb = wsm + (n % 3) * 8192;
#pragma unroll
        for (int nt = 0; nt < 4; nt++) {
            const int p = warp * 32 + nt * 8 + r;
#pragma unroll
            for (int ks = 0; ks < 2; ks++) {
                int col = (ks * 4 + q) ^ ((p & 1) << 2);
                float4 bf = *reinterpret_cast<const float4*>(wb + p * 32 + col * 4);
                __half2 h0 = __floats2half2_rn(bf.x, bf.y);
                __half2 h1 = __floats2half2_rn(bf.z, bf.w);
                uint32_t b0 = *reinterpret_cast<uint32_t*>(&h0);
                uint32_t b1 = *reinterpret_cast<uint32_t*>(&h1);
                mma16816(d[nt][0], A[0][ks][0], A[0][ks][1], A[0][ks][2], A[0][ks][3], b0, b1);
                mma16816(d[nt][1], A[1][ks][0], A[1][ks][1], A[1][ks][2], A[1][ks][3], b0, b1);
            }
        }

        // Epilogue: s1 accumulate + direct half2 stores (sector-aligned)
#pragma unroll
        for (int nt = 0; nt < 4; nt++)
#pragma unroll
            for (int bt = 0; bt < 2; bt++) {
#pragma unroll
                for (int jj = 0; jj < 4; jj++) sacc[nt][bt][jj] += d[nt][bt][jj];
                __half2 lo = __floats2half2_rn(d[nt][bt][0], d[nt][bt][1]);
                __half2 hi = __floats2half2_rn(d[nt][bt][2], d[nt][bt][3]);
                __half* base =
                    g_uhat + (long)c * 65536 + chunk * 256 + warp * 32 + nt * 8 + 2 * q;
                *reinterpret_cast<__half2*>(base + (bt * 16 + r) * 2048) = lo;
                *reinterpret_cast<__half2*>(base + (bt * 16 + r + 8) * 2048) = hi;
            }

        if (cc == 7) {   // s1 partials (c1 = 1/64)
            float* sp = g_sparts + (long)blockIdx.x * 65536 + chunk * 256;
#pragma unroll
            for (int nt = 0; nt < 4; nt++)
#pragma unroll
                for (int bt = 0; bt < 2; bt++) {
                    int col = warp * 32 + nt * 8 + 2 * q;
                    int row = bt * 16 + r;
                    *reinterpret_cast<float2*>(sp + row * 2048 + col) =
                        make_float2(sacc[nt][bt][0] * 0.015625f, sacc[nt][bt][1] * 0.015625f);
                    *reinterpret_cast<float2*>(sp + (row + 8) * 2048 + col) =
                        make_float2(sacc[nt][bt][2] * 0.015625f, sacc[nt][bt][3] * 0.015625f);
                }
        }
    }
}

// ---------------- squash (+ write_vh flag) ----------------
__global__ void k_squash(int nparts, float* __restrict__ out_ext, int use_ext,
                         int write_vh) {
    int e = blockIdx.x * 256 + threadIdx.x;
    float a0 = 0.f, a1 = 0.f, a2 = 0.f, a3 = 0.f;
    int p = 0;
    for (; p + 3 < nparts; p += 4) {
        a0 += g_sparts[(long)(p + 0) * 65536 + e];
        a1 += g_sparts[(long)(p + 1) * 65536 + e];
        a2 += g_sparts[(long)(p + 2) * 65536 + e];
        a3 += g_sparts[(long)(p + 3) * 65536 + e];
    }
    for (; p < nparts; p++) a0 += g_sparts[(long)p * 65536 + e];
    float s = (a0 + a1) + (a2 + a3);
    float sq = s * s;
#pragma unroll
    for (int off = 16; off > 0; off >>= 1)
        sq += __shfl_xor_sync(0xffffffffu, sq, off);
    float scale = sq / ((1.f + sq) * sqrtf(sq + 1e-8f));
    float res = s * scale;
    if (use_ext) out_ext[e] = res;
    if (write_vh) g_vh[e] = __float2half_rn(res);
}

// ---------------- fused routing step (proven, verbatim) ----------------
// smem: vh 64KB | stage[2] 2x64KB | agree 1KB
#define FS_STAGE 65536
#define FS_AGREE 196608
#define FS_TOT 197632

__global__ __launch_bounds__(512, 1) __cluster_dims__(2, 1, 1)
void k_fused(int add_prior, int store_b) {
    extern __shared__ char fsm[];
    __half* vh_sm = reinterpret_cast<__half*>(fsm);
    float* agree_sm = reinterpret_cast<float*>(fsm + FS_AGREE);

    const int tid = threadIdx.x;
    const int w = tid >> 5, l = tid & 31;
    const int u = w * 4 + (l >> 3);    // thread's unit
    const int oq = l & 7;              // o-quad
    const int r = blockIdx.x & 1, peer = r ^ 1;
    const int cid = blockIdx.x >> 1, nclus = gridDim.x >> 1;
    const int c_start = (cid * 2048) / nclus;
    const int c_end = ((cid + 1) * 2048) / nclus;
    const int toff = u * 32 + oq * 4;  // + bb*2048 (half units)

    // Load this CTA's b-half of v (fp16), coalesced
    {
        const uint4* src = reinterpret_cast<const uint4*>(g_vh + r * 32768);
        uint4* dst = reinterpret_cast<uint4*>(vh_sm);
        for (int idx = tid; idx < 4096; idx += 512) dst[idx] = src[idx];
    }

    auto stage_issue = [&](int c, int buf) {
        const char* src = reinterpret_cast<const char*>(
            g_uhat + (long)c * 65536 + (long)r * 32768);
        uint32_t dst = (uint32_t)__cvta_generic_to_shared(fsm + FS_STAGE + buf * 65536);
#pragma unroll
        for (int it = 0; it < 8; it++) {
            int off = (it * 512 + tid) * 16;
            asm volatile("cp.async.cg.shared.global [%0], [%1], 16;"
                         :: "r"(dst + off), "l"(src + off) : "memory");
        }
        asm volatile("cp.async.commit_group;" ::: "memory");
    };
    stage_issue(c_start, 0);
    if (c_start + 1 < c_end) stage_issue(c_start + 1, 1);
    else asm volatile("cp.async.commit_group;" ::: "memory");

    float4 sacc[16];
#pragma unroll
    for (int bb = 0; bb < 16; bb++) sacc[bb] = make_float4(0.f, 0.f, 0.f, 0.f);

    __syncthreads();   // vh_sm ready

    for (int c = c_start; c < c_end; c++) {
        const int buf = (c - c_start) & 1;
        const int par = c & 1;
        const __half* st = reinterpret_cast<const __half*>(fsm + FS_STAGE + buf * 65536);

        asm volatile("cp.async.wait_group 1;" ::: "memory");
        __syncthreads();

        // Phase A: agree, LDS.64 on both stage and v
        float a = 0.f;
#pragma unroll
        for (int bb = 0; bb < 16; bb++) {
            uint2 hu = *reinterpret_cast<const uint2*>(st + bb * 2048 + toff);
            uint2 hv = *reinterpret_cast<const uint2*>(vh_sm + bb * 2048 + toff);
            float2 f0 = __half22float2(*reinterpret_cast<const __half2*>(&hu.x));
            float2 f1 = __half22float2(*reinterpret_cast<const __half2*>(&hu.y));
            float2 v0 = __half22float2(*reinterpret_cast<const __half2*>(&hv.x));
            float2 v1 = __half22float2(*reinterpret_cast<const __half2*>(&hv.y));
            a += f0.x * v0.x + f0.y * v0.y + f1.x * v1.x + f1.y * v1.y;
        }
        a += __shfl_xor_sync(0xffffffffu, a, 4);
        a += __shfl_xor_sync(0xffffffffu, a, 2);
        a += __shfl_xor_sync(0xffffffffu, a, 1);

        if ((l & 7) == 0) {
            agree_sm[(par * 2 + r) * 64 + u] = a;
            unsigned int la = (unsigned int)__cvta_generic_to_shared(
                &agree_sm[(par * 2 + r) * 64 + u]);
            asm volatile(
                "{.reg .b32 ra; mapa.shared::cluster.u32 ra, %0, %1;"
                " st.shared::cluster.f32 [ra], %2;}"
                :: "r"(la), "r"(peer), "f"(a));
        }
        asm volatile("barrier.cluster.arrive.aligned;" ::: "memory");
        asm volatile("barrier.cluster.wait.aligned;" ::: "memory");

        // Merge halves, logits, softmax over 64 u (redundant per warp)
        float a0 = (agree_sm[(par * 2) * 64 + l] +
                    agree_sm[(par * 2 + 1) * 64 + l]) * 0.03125f;
        float a1 = (agree_sm[(par * 2) * 64 + 32 + l] +
                    agree_sm[(par * 2 + 1) * 64 + 32 + l]) * 0.03125f;
        if (add_prior) {
            a0 += g_b[c * 64 + l];
            a1 += g_b[c * 64 + 32 + l];
        }
        if (store_b && r == 0 && w == 0) {
            g_b[c * 64 + l] = a0;
            g_b[c * 64 + 32 + l] = a1;
        }
        float mx = fmaxf(a0, a1);
#pragma unroll
        for (int off = 16; off > 0; off >>= 1)
            mx = fmaxf(mx, __shfl_xor_sync(0xffffffffu, mx, off));
        float e0 = expf(a0 - mx), e1 = expf(a1 - mx);
        float sume = e0 + e1;
#pragma unroll
        for (int off = 16; off > 0; off >>= 1)
            sume += __shfl_xor_sync(0xffffffffu, sume, off);
        float inv = 1.f / sume;
        float c0v = e0 * inv, c1v = e1 * inv;
        float cv = __shfl_sync(0xffffffffu, (w < 8) ? c0v : c1v, u & 31);

        // Phase C: s accumulation (LDS.64 re-read of stage)
#pragma unroll
        for (int bb = 0; bb < 16; bb++) {
            uint2 hu = *reinterpret_cast<const uint2*>(st + bb * 2048 + toff);
            float2 f0 = __half22float2(*reinterpret_cast<const __half2*>(&hu.x));
            float2 f1 = __half22float2(*reinterpret_cast<const __half2*>(&hu.y));
            sacc[bb].x += cv * f0.x;
            sacc[bb].y += cv * f0.y;
            sacc[bb].z += cv * f1.x;
            sacc[bb].w += cv * f1.y;
        }

        __syncthreads();
        if (c + 2 < c_end) stage_issue(c + 2, buf);
        else asm volatile("cp.async.commit_group;" ::: "memory");
    }

    float* sp = g_sparts + (long)cid * 65536 + (long)(r * 16) * 2048 + u * 32 + oq * 4;
#pragma unroll
    for (int bb = 0; bb < 16; bb++)
        *reinterpret_cast<float4*>(sp + bb * 2048) = sacc[bb];
}

// ---------------------------------------------------------------------------

extern "C" void kernel_launch(void* const* d_in, const int* in_sizes, int n_in,
                              void* d_out, int out_size) {
    const float* x = (const float*)d_in[0];
    const float* w = (const float*)d_in[1];
    if (in_sizes[0] > in_sizes[1]) { const float* t = x; x = w; w = t; }
    float* out = (float*)d_out;

    cudaFuncSetAttribute(k_gemm_mma, cudaFuncAttributeMaxDynamicSharedMemorySize, GM_TOT);
    cudaFuncSetAttribute(k_fused, cudaFuncAttributeMaxDynamicSharedMemorySize, FS_TOT);

    k_nop<<<1, 32>>>();                          // #1 (ncu alignment)
    k_gemm_mma<<<256, 256, GM_TOT>>>(x, w);      // #2: u_hat(fp16) + s1 partials (256)
    k_squash<<<256, 256>>>(256, out, 0, 1);      // #3: v1 (+ fp16 copy)
    k_fused<<<148, 512, FS_TOT>>>(0, 1);         // #4: agree1 -> b2 -> c2 -> s2 (74 slots)
    k_squash<<<256, 256>>>(74, out, 0, 1);       // #5: v2 (+ fp16 copy)
    k_fused<<<148, 512, FS_TOT>>>(1, 0);         // #6: agree2 -> b3 -> c3 -> s3 (ncu)
    k_squash<<<256, 256>>>(74, out, 1, 0);       // #7: v3 -> output (vh dead)
}

// round 16
// speedup vs baseline: 1.0590x; 1.0590x over previous
#include <cuda_runtime.h>
#include <cuda_fp16.h>
#include <cstdint>

// CapsuleLayer: B=32, I=32, C=2048, U=64, O=32, 3 routing iterations.
// R16 = R14 (360.5us, proven) + ONE delta in k_fused: channel-slice staging via
// 1-D cp.async.bulk + mbarrier (1 instr / 64KB) instead of 4096 cp.async.cg —
// removes the LDGSTS issue bottleneck identified by per-channel cycle accounting.
//  k_gemm_mma : fp16 mma.sync m16n8k16; 2-stage cp.async W staging. [R14]
//  k_squash   : reduce s partials -> squash -> v (+ optional fp16 copy). [R14]
//  k_fused    : 2-CTA cluster, bulk-DMA double-buffered staging, o-quad map.

__device__ __half g_uhat[134217728];  // 256 MB (c,b,u,o): c*65536 + b*2048 + uo
__device__ float g_sparts[16777216];  // 256 slots x 65536 (b*2048 + uo)
__device__ __half g_vh[65536];        // v fp16 (b,u,o)
__device__ float g_b[131072];         // routing logits (C,U)

__global__ void k_nop() {}

// ---------------- gemm (R14 verbatim) ----------------
#define WSTAGE 32768
#define SM_TOT (2 * WSTAGE + 16384)

__device__ __forceinline__ void mma16816(float d[4], uint32_t a0, uint32_t a1,
                                         uint32_t a2, uint32_t a3,
                                         uint32_t b0, uint32_t b1) {
    asm volatile(
        "mma.sync.aligned.m16n8k16.row.col.f32.f16.f16.f32 "
        "{%0,%1,%2,%3}, {%4,%5,%6,%7}, {%8,%9}, {%0,%1,%2,%3};"
        : "+f"(d[0]), "+f"(d[1]), "+f"(d[2]), "+f"(d[3])
        : "r"(a0), "r"(a1), "r"(a2), "r"(a3), "r"(b0), "r"(b1));
}

__global__ __launch_bounds__(256, 2) void k_gemm_mma(const float* __restrict__ x,
                                                     const float* __restrict__ w) {
    extern __shared__ char smem[];
    float* wsm = reinterpret_cast<float*>(smem);
    __half* x_h = reinterpret_cast<__half*>(smem + 2 * WSTAGE);
    const int tid = threadIdx.x;
    const int warp = tid >> 5, lane = tid & 31;
    const int r = lane >> 2, q = lane & 3;
    const int c0 = blockIdx.x * 8;

    auto issue = [&](int n) {
        const float* src = w + ((long)(c0 + (n & 7)) * 2048 + (long)(n >> 3) * 256) * 32;
        char* dst = smem + (n & 1) * WSTAGE;
#pragma unroll
        for (int it = 0; it < 8; it++) {
            int lin = it * 256 + tid;
            int row = lin >> 3, cq = lin & 7;
            int col = cq ^ ((row & 1) << 2);   // parity swizzle -> conflict-free LDS.128
            asm volatile("cp.async.cg.shared.global [%0], [%1], 16;"
                :: "r"((uint32_t)__cvta_generic_to_shared(dst + row * 128 + col * 16)),
                   "l"(src + row * 32 + cq * 4) : "memory");
        }
        asm volatile("cp.async.commit_group;" ::: "memory");
    };
    issue(0);

    // Stage x -> fp16 smem: x_h[cc][b][i]
    for (int idx = tid; idx < 8192; idx += 256) {
        int cc = idx & 7, bi = idx >> 3;
        x_h[cc * 1024 + bi] = __float2half_rn(x[bi * 2048 + c0 + cc]);
    }

    float sacc[4][2][4];

    for (int n = 0; n < 64; n++) {
        const int cc = n & 7, chunk = n >> 3;
        const int c = c0 + cc;

        asm volatile("cp.async.wait_group 0;" ::: "memory");
        __syncthreads();
        if (n < 63) issue(n + 1);

        if (cc == 0) {
#pragma unroll
            for (int nt = 0; nt < 4; nt++)
#pragma unroll
                for (int bt = 0; bt < 2; bt++)
#pragma unroll
                    for (int jj = 0; jj < 4; jj++) sacc[nt][bt][jj] = 0.f;
        }

        // A fragments (logical-k permutation; matches B below)
        uint32_t A[2][2][4];
#pragma unroll
        for (int bt = 0; bt < 2; bt++)
#pragma unroll
            for (int ks = 0; ks < 2; ks++) {
                uint2 v1 = *reinterpret_cast<const uint2*>(
                    &x_h[cc * 1024 + (bt * 16 + r) * 32 + ks * 16 + q * 4]);
                uint2 v2 = *reinterpret_cast<const uint2*>(
                    &x_h[cc * 1024 + (bt * 16 + r + 8) * 32 + ks * 16 + q * 4]);
                A[bt][ks][0] = v1.x;
                A[bt][ks][1] = v2.x;
                A[bt][ks][2] = v1.y;
                A[bt][ks][3] = v2.y;
            }

        float d[4][2][4];
#pragma unroll
        for (int nt = 0; nt < 4; nt++)
#pragma unroll
            for (int bt = 0; bt < 2; bt++)
#pragma unroll
                for (int jj = 0; jj < 4; jj++) d[nt][bt][jj] = 0.f;

        const float* wb = wsm + (n & 1) * 8192;
#pragma unroll
        for (int nt = 0; nt < 4; nt++) {
            const int p = warp * 32 + nt * 8 + r;
#pragma unroll
            for (int ks = 0; ks < 2; ks++) {
                int col = (ks * 4 + q) ^ ((p & 1) << 2);
                float4 bf = *reinterpret_cast<const float4*>(wb + p * 32 + col * 4);
                __half2 h0 = __floats2half2_rn(bf.x, bf.y);
                __half2 h1 = __floats2half2_rn(bf.z, bf.w);
                uint32_t b0 = *reinterpret_cast<uint32_t*>(&h0);
                uint32_t b1 = *reinterpret_cast<uint32_t*>(&h1);
                mma16816(d[nt][0], A[0][ks][0], A[0][ks][1], A[0][ks][2], A[0][ks][3], b0, b1);
                mma16816(d[nt][1], A[1][ks][0], A[1][ks][1], A[1][ks][2], A[1][ks][3], b0, b1);
            }
        }

        // Epilogue: s1 accumulate + direct half2 stores (sector-aligned)
#pragma unroll
        for (int nt = 0; nt < 4; nt++)
#pragma unroll
            for (int bt = 0; bt < 2; bt++) {
#pragma unroll
                for (int jj = 0; jj < 4; jj++) sacc[nt][bt][jj] += d[nt][bt][jj];
                __half2 lo = __floats2half2_rn(d[nt][bt][0], d[nt][bt][1]);
                __half2 hi = __floats2half2_rn(d[nt][bt][2], d[nt][bt][3]);
                __half* base =
                    g_uhat + (long)c * 65536 + chunk * 256 + warp * 32 + nt * 8 + 2 * q;
                *reinterpret_cast<__half2*>(base + (bt * 16 + r) * 2048) = lo;
                *reinterpret_cast<__half2*>(base + (bt * 16 + r + 8) * 2048) = hi;
            }

        if (cc == 7) {   // s1 partials (c1 = 1/64)
            float* sp = g_sparts + (long)blockIdx.x * 65536 + chunk * 256;
#pragma unroll
            for (int nt = 0; nt < 4; nt++)
#pragma unroll
                for (int bt = 0; bt < 2; bt++) {
                    int col = warp * 32 + nt * 8 + 2 * q;
                    int row = bt * 16 + r;
                    *reinterpret_cast<float2*>(sp + row * 2048 + col) =
                        make_float2(sacc[nt][bt][0] * 0.015625f, sacc[nt][bt][1] * 0.015625f);
                    *reinterpret_cast<float2*>(sp + (row + 8) * 2048 + col) =
                        make_float2(sacc[nt][bt][2] * 0.015625f, sacc[nt][bt][3] * 0.015625f);
                }
        }
    }
}

// ---------------- squash (R14 verbatim) ----------------
__global__ void k_squash(int nparts, float* __restrict__ out_ext, int use_ext,
                         int write_vh) {
    int e = blockIdx.x * 256 + threadIdx.x;
    float a0 = 0.f, a1 = 0.f, a2 = 0.f, a3 = 0.f;
    int p = 0;
    for (; p + 3 < nparts; p += 4) {
        a0 += g_sparts[(long)(p + 0) * 65536 + e];
        a1 += g_sparts[(long)(p + 1) * 65536 + e];
        a2 += g_sparts[(long)(p + 2) * 65536 + e];
        a3 += g_sparts[(long)(p + 3) * 65536 + e];
    }
    for (; p < nparts; p++) a0 += g_sparts[(long)p * 65536 + e];
    float s = (a0 + a1) + (a2 + a3);
    float sq = s * s;
#pragma unroll
    for (int off = 16; off > 0; off >>= 1)
        sq += __shfl_xor_sync(0xffffffffu, sq, off);
    float scale = sq / ((1.f + sq) * sqrtf(sq + 1e-8f));
    float res = s * scale;
    if (use_ext) out_ext[e] = res;
    if (write_vh) g_vh[e] = __float2half_rn(res);
}

// ---------------- fused routing step (bulk-DMA staging) ----------------
// smem: vh 64KB | stage[2] 2x64KB | agree 1KB | mbar[2] 16B
#define FS_STAGE 65536
#define FS_AGREE 196608
#define FS_MBAR 197632
#define FS_TOT 197664

__global__ __launch_bounds__(512, 1) __cluster_dims__(2, 1, 1)
void k_fused(int add_prior, int store_b) {
    extern __shared__ char fsm[];
    __half* vh_sm = reinterpret_cast<__half*>(fsm);
    float* agree_sm = reinterpret_cast<float*>(fsm + FS_AGREE);

    const int tid = threadIdx.x;
    const int w = tid >> 5, l = tid & 31;
    const int u = w * 4 + (l >> 3);    // thread's unit
    const int oq = l & 7;              // o-quad
    const int r = blockIdx.x & 1, peer = r ^ 1;
    const int cid = blockIdx.x >> 1, nclus = gridDim.x >> 1;
    const int c_start = (cid * 2048) / nclus;
    const int c_end = ((cid + 1) * 2048) / nclus;
    const int toff = u * 32 + oq * 4;  // + bb*2048 (half units)
    const uint32_t mbar0 = (uint32_t)__cvta_generic_to_shared(fsm + FS_MBAR);

    if (tid == 0) {
        asm volatile("mbarrier.init.shared.b64 [%0], 1;" :: "r"(mbar0) : "memory");
        asm volatile("mbarrier.init.shared.b64 [%0], 1;" :: "r"(mbar0 + 8) : "memory");
    }

    // Load this CTA's b-half of v (fp16), coalesced
    {
        const uint4* src = reinterpret_cast<const uint4*>(g_vh + r * 32768);
        uint4* dst = reinterpret_cast<uint4*>(vh_sm);
        for (int idx = tid; idx < 4096; idx += 512) dst[idx] = src[idx];
    }
    __syncthreads();   // mbarriers initialized + vh_sm ready

    // One-instruction 64KB slice DMA, completion via mbarrier complete_tx
    auto bulk_issue = [&](int c, int buf) {
        if (tid == 0) {
            uint32_t mb = mbar0 + buf * 8;
            asm volatile("mbarrier.arrive.expect_tx.shared.b64 _, [%0], %1;"
                         :: "r"(mb), "r"(65536u) : "memory");
            const char* src = reinterpret_cast<const char*>(
                g_uhat + (long)c * 65536 + (long)r * 32768);
            uint32_t dst = (uint32_t)__cvta_generic_to_shared(fsm + FS_STAGE + buf * 65536);
            asm volatile(
                "cp.async.bulk.shared::cluster.global.mbarrier::complete_tx::bytes "
                "[%0], [%1], %2, [%3];"
                :: "r"(dst), "l"(src), "r"(65536u), "r"(mb) : "memory");
        }
    };
    auto mwait = [&](int buf, uint32_t par) {
        uint32_t mb = mbar0 + buf * 8, done;
        asm volatile(
            "{\n\t.reg .pred p;\n\t"
            "mbarrier.try_wait.parity.acquire.cta.shared::cta.b64 p, [%1], %2;\n\t"
            "selp.b32 %0, 1, 0, p;\n\t}"
            : "=r"(done) : "r"(mb), "r"(par) : "memory");
        if (!done) {
            asm volatile(
                "{\n\t.reg .pred P1;\n\t"
                "W1_%=:\n\t"
                "mbarrier.try_wait.parity.acquire.cta.shared::cta.b64 P1, [%0], %1, 0x989680;\n\t"
                "@P1 bra.uni W2_%=;\n\t"
                "bra.uni W1_%=;\n\t"
                "W2_%=:\n\t}"
                :: "r"(mb), "r"(par) : "memory");
        }
    };

    bulk_issue(c_start, 0);
    if (c_start + 1 < c_end) bulk_issue(c_start + 1, 1);

    float4 sacc[16];
#pragma unroll
    for (int bb = 0; bb < 16; bb++) sacc[bb] = make_float4(0.f, 0.f, 0.f, 0.f);

    for (int c = c_start; c < c_end; c++) {
        const int m = c - c_start;
        const int buf = m & 1;
        const int par = c & 1;
        const __half* st = reinterpret_cast<const __half*>(fsm + FS_STAGE + buf * 65536);

        mwait(buf, (m >> 1) & 1);   // slice c landed (phase = use count parity)

        // Phase A: agree, LDS.64 on both stage and v
        float a = 0.f;
#pragma unroll
        for (int bb = 0; bb < 16; bb++) {
            uint2 hu = *reinterpret_cast<const uint2*>(st + bb * 2048 + toff);
            uint2 hv = *reinterpret_cast<const uint2*>(vh_sm + bb * 2048 + toff);
            float2 f0 = __half22float2(*reinterpret_cast<const __half2*>(&hu.x));
            float2 f1 = __half22float2(*reinterpret_cast<const __half2*>(&hu.y));
            float2 v0 = __half22float2(*reinterpret_cast<const __half2*>(&hv.x));
            float2 v1 = __half22float2(*reinterpret_cast<const __half2*>(&hv.y));
            a += f0.x * v0.x + f0.y * v0.y + f1.x * v1.x + f1.y * v1.y;
        }
        a += __shfl_xor_sync(0xffffffffu, a, 4);
        a += __shfl_xor_sync(0xffffffffu, a, 2);
        a += __shfl_xor_sync(0xffffffffu, a, 1);

        if ((l & 7) == 0) {
            agree_sm[(par * 2 + r) * 64 + u] = a;
            unsigned int la = (unsigned int)__cvta_generic_to_shared(
                &agree_sm[(par * 2 + r) * 64 + u]);
            asm volatile(
                "{.reg .b32 ra; mapa.shared::cluster.u32 ra, %0, %1;"
                " st.shared::cluster.f32 [ra], %2;}"
                :: "r"(la), "r"(peer), "f"(a));
        }
        asm volatile("barrier.cluster.arrive.aligned;" ::: "memory");
        asm volatile("barrier.cluster.wait.aligned;" ::: "memory");

        // Merge halves, logits, softmax over 64 u (redundant per warp)
        float a0 = (agree_sm[(par * 2) * 64 + l] +
                    agree_sm[(par * 2 + 1) * 64 + l]) * 0.03125f;
        float a1 = (agree_sm[(par * 2) * 64 + 32 + l] +
                    agree_sm[(par * 2 + 1) * 64 + 32 + l]) * 0.03125f;
        if (add_prior) {
            a0 += g_b[c * 64 + l];
            a1 += g_b[c * 64 + 32 + l];
        }
        if (store_b && r == 0 && w == 0) {
            g_b[c * 64 + l] = a0;
            g_b[c * 64 + 32 + l] = a1;
        }
        float mx = fmaxf(a0, a1);
#pragma unroll
        for (int off = 16; off > 0; off >>= 1)
            mx = fmaxf(mx, __shfl_xor_sync(0xffffffffu, mx, off));
        float e0 = expf(a0 - mx), e1 = expf(a1 - mx);
        float sume = e0 + e1;
#pragma unroll
        for (int off = 16; off > 0; off >>= 1)
            sume += __shfl_xor_sync(0xffffffffu, sume, off);
        float inv = 1.f / sume;
        float c0v = e0 * inv, c1v = e1 * inv;
        float cv = __shfl_sync(0xffffffffu, (w < 8) ? c0v : c1v, u & 31);

        // Phase C: s accumulation (LDS.64 re-read of stage)
#pragma unroll
        for (int bb = 0; bb < 16; bb++) {
            uint2 hu = *reinterpret_cast<const uint2*>(st + bb * 2048 + toff);
            float2 f0 = __half22float2(*reinterpret_cast<const __half2*>(&hu.x));
            float2 f1 = __half22float2(*reinterpret_cast<const __half2*>(&hu.y));
            sacc[bb].x += cv * f0.x;
            sacc[bb].y += cv * f0.y;
            sacc[bb].z += cv * f1.x;
            sacc[bb].w += cv * f1.y;
        }

        __syncthreads();                          // all threads done reading buf
        if (c + 2 < c_end) bulk_issue(c + 2, buf);
    }

    float* sp = g_sparts + (long)cid * 65536 + (long)(r * 16) * 2048 + u * 32 + oq * 4;
#pragma unroll
    for (int bb = 0; bb < 16; bb++)
        *reinterpret_cast<float4*>(sp + bb * 2048) = sacc[bb];
}

// ---------------------------------------------------------------------------

extern "C" void kernel_launch(void* const* d_in, const int* in_sizes, int n_in,
                              void* d_out, int out_size) {
    const float* x = (const float*)d_in[0];
    const float* w = (const float*)d_in[1];
    if (in_sizes[0] > in_sizes[1]) { const float* t = x; x = w; w = t; }
    float* out = (float*)d_out;

    cudaFuncSetAttribute(k_gemm_mma, cudaFuncAttributeMaxDynamicSharedMemorySize, SM_TOT);
    cudaFuncSetAttribute(k_fused, cudaFuncAttributeMaxDynamicSharedMemorySize, FS_TOT);

    k_nop<<<1, 32>>>();                          // #1 (ncu alignment)
    k_gemm_mma<<<256, 256, SM_TOT>>>(x, w);      // #2: u_hat(fp16) + s1 partials (256)
    k_squash<<<256, 256>>>(256, out, 0, 1);      // #3: v1 (+ fp16 copy)
    k_fused<<<148, 512, FS_TOT>>>(0, 1);         // #4: agree1 -> b2 -> c2 -> s2 (74 slots)
    k_squash<<<256, 256>>>(74, out, 0, 1);       // #5: v2 (+ fp16 copy)
    k_fused<<<148, 512, FS_TOT>>>(1, 0);         // #6: agree2 -> b3 -> c3 -> s3 (ncu)
    k_squash<<<256, 256>>>(74, out, 1, 0);       // #7: v3 -> output (vh dead)
}